// round 1
// baseline (speedup 1.0000x reference)
#include <cuda_runtime.h>
#include <math.h>

// Problem constants
#define BATCH    2
#define T_SEQ    2048
#define D_MODEL  1024
#define N_HEADS  16
#define HEAD_DIM 64
#define M_TOTAL  (BATCH * T_SEQ)          // 4096 rows
#define QKV_LD   (3 * D_MODEL)            // 3072

// Scratch (allocation-free rule: __device__ globals)
__device__ float g_qkv [M_TOTAL * QKV_LD];   // [4096, 3072] : Q|K|V interleaved per row
__device__ float g_attn[M_TOTAL * D_MODEL];  // [4096, 1024] : attention output in [B,T,C]

// ---------------------------------------------------------------------------
// SGEMM: C[M,N] = A[M,K] @ B[K,N], all row-major, fp32.
// 128x128 block tile, K-step 8, 256 threads, 8x8 per-thread micro-tile.
// Requires M%128==0, N%128==0, K%8==0 (true for all three calls).
// ---------------------------------------------------------------------------
__global__ __launch_bounds__(256) void sgemm128(const float* __restrict__ A,
                                                const float* __restrict__ B,
                                                float* __restrict__ C,
                                                int M, int N, int K) {
    __shared__ float As[8][128];   // transposed A tile: As[k][m]
    __shared__ float Bs[8][128];   // Bs[k][n]

    const int tid = threadIdx.x;
    const int row0 = blockIdx.y * 128;
    const int col0 = blockIdx.x * 128;
    const int tx = tid & 15;       // 0..15 -> col groups
    const int ty = tid >> 4;       // 0..15 -> row groups

    // load mappings
    const int a_row = tid >> 1;            // 0..127
    const int a_k4  = (tid & 1) * 4;       // 0 or 4
    const int b_kr  = tid >> 5;            // 0..7
    const int b_c4  = (tid & 31) * 4;      // 0..124

    float acc[8][8];
#pragma unroll
    for (int i = 0; i < 8; i++)
#pragma unroll
        for (int j = 0; j < 8; j++) acc[i][j] = 0.f;

    for (int k0 = 0; k0 < K; k0 += 8) {
        float4 av = *(const float4*)&A[(size_t)(row0 + a_row) * K + k0 + a_k4];
        float4 bv = *(const float4*)&B[(size_t)(k0 + b_kr) * N + col0 + b_c4];
        As[a_k4 + 0][a_row] = av.x;
        As[a_k4 + 1][a_row] = av.y;
        As[a_k4 + 2][a_row] = av.z;
        As[a_k4 + 3][a_row] = av.w;
        *(float4*)&Bs[b_kr][b_c4] = bv;
        __syncthreads();

#pragma unroll
        for (int kk = 0; kk < 8; kk++) {
            float a[8], b[8];
            *(float4*)&a[0] = *(const float4*)&As[kk][ty * 8];
            *(float4*)&a[4] = *(const float4*)&As[kk][ty * 8 + 4];
            // columns split: [tx*4 .. tx*4+3] and [64 + tx*4 .. +3] (reduces smem bank conflicts)
            *(float4*)&b[0] = *(const float4*)&Bs[kk][tx * 4];
            *(float4*)&b[4] = *(const float4*)&Bs[kk][64 + tx * 4];
#pragma unroll
            for (int i = 0; i < 8; i++)
#pragma unroll
                for (int j = 0; j < 8; j++) acc[i][j] = fmaf(a[i], b[j], acc[i][j]);
        }
        __syncthreads();
    }

#pragma unroll
    for (int i = 0; i < 8; i++) {
        const int row = row0 + ty * 8 + i;
        float4 c0 = make_float4(acc[i][0], acc[i][1], acc[i][2], acc[i][3]);
        float4 c1 = make_float4(acc[i][4], acc[i][5], acc[i][6], acc[i][7]);
        *(float4*)&C[(size_t)row * N + col0 + tx * 4]      = c0;
        *(float4*)&C[(size_t)row * N + col0 + 64 + tx * 4] = c1;
    }
}

// ---------------------------------------------------------------------------
// Causal flash attention, fp32 SIMT.
// grid = (T/64, B*H). Block: 256 threads, 64-query tile, 64-key tiles.
// Thread layout: query = tid/4 (0..63), sub = tid%4 ; thread owns 16 key-cols
// of S and 16 head-dims of O. The K tile (transposed) is aliased by the P tile
// to fit 3x 64x68 fp32 buffers in dynamic smem (~52 KB).
// ---------------------------------------------------------------------------
#define FA_STRIDE 68   // 64 + 4 pad, keeps float4 alignment, breaks conflicts

__global__ __launch_bounds__(256) void flash_attn_kernel() {
    extern __shared__ float sm[];
    float* Qs  = sm;                     // [64][68]  Q natural layout
    float* KPs = sm + 64 * FA_STRIDE;    // [64][68]  K^T (d-major), later aliased as P[q][k]
    float* Vs  = sm + 2 * 64 * FA_STRIDE;// [64][68]  V natural layout

    const int tid = threadIdx.x;
    const int qt  = blockIdx.x;          // query tile 0..31
    const int bh  = blockIdx.y;          // 0..31
    const int b   = bh >> 4;
    const int h   = bh & 15;

    const float* base = g_qkv + (size_t)b * T_SEQ * QKV_LD + h * HEAD_DIM;
    const float* Qg = base;
    const float* Kg = base + D_MODEL;
    const float* Vg = base + 2 * D_MODEL;

    const int query = tid >> 2;          // 0..63
    const int sub   = tid & 3;           // 0..3
    const int qg    = qt * 64 + query;   // global query index (within batch)

    // ---- load Q tile (64x64, float4) ----
#pragma unroll
    for (int i = 0; i < 4; i++) {
        int ff = tid + i * 256;          // 1024 float4 total
        int r  = ff >> 4;
        int d4 = (ff & 15) * 4;
        float4 v = *(const float4*)&Qg[(size_t)(qt * 64 + r) * QKV_LD + d4];
        *(float4*)&Qs[r * FA_STRIDE + d4] = v;
    }

    const float NEG_INF = __int_as_float(0xff800000u);
    float m = NEG_INF, l = 0.f;
    float o[16];
#pragma unroll
    for (int i = 0; i < 16; i++) o[i] = 0.f;
    const float scale = 0.125f;          // 1/sqrt(64)

    for (int kt = 0; kt <= qt; kt++) {
        __syncthreads();                 // prior P/V reads complete (also covers Q load, iter 0)
        // ---- load K (transposed -> KPs[d][k]) and V (natural) ----
#pragma unroll
        for (int i = 0; i < 4; i++) {
            int ff = tid + i * 256;
            int r  = ff >> 4;
            int d4 = (ff & 15) * 4;
            float4 kv = *(const float4*)&Kg[(size_t)(kt * 64 + r) * QKV_LD + d4];
            KPs[(d4 + 0) * FA_STRIDE + r] = kv.x;
            KPs[(d4 + 1) * FA_STRIDE + r] = kv.y;
            KPs[(d4 + 2) * FA_STRIDE + r] = kv.z;
            KPs[(d4 + 3) * FA_STRIDE + r] = kv.w;
            float4 vv = *(const float4*)&Vg[(size_t)(kt * 64 + r) * QKV_LD + d4];
            *(float4*)&Vs[r * FA_STRIDE + d4] = vv;
        }
        __syncthreads();

        // ---- S = (Q K^T) * scale, this thread: 16 keys [sub*16 .. sub*16+15] ----
        float s[16];
#pragma unroll
        for (int j = 0; j < 16; j++) s[j] = 0.f;
        for (int d = 0; d < 64; d++) {
            float qv = Qs[query * FA_STRIDE + d];
            const float* kr = &KPs[d * FA_STRIDE + sub * 16];
#pragma unroll
            for (int j = 0; j < 16; j++) s[j] = fmaf(qv, kr[j], s[j]);
        }

        const bool diag = (kt == qt);
#pragma unroll
        for (int j = 0; j < 16; j++) {
            s[j] *= scale;
            if (diag) {
                int kg = kt * 64 + sub * 16 + j;
                if (kg > qg) s[j] = NEG_INF;
            }
        }

        // ---- online softmax (row = quad of 4 lanes) ----
        float tmax = s[0];
#pragma unroll
        for (int j = 1; j < 16; j++) tmax = fmaxf(tmax, s[j]);
        tmax = fmaxf(tmax, __shfl_xor_sync(0xffffffffu, tmax, 1, 4));
        tmax = fmaxf(tmax, __shfl_xor_sync(0xffffffffu, tmax, 2, 4));
        float m_new = fmaxf(m, tmax);
        float alpha = __expf(m - m_new);
        float psum = 0.f;
#pragma unroll
        for (int j = 0; j < 16; j++) {
            float p = __expf(s[j] - m_new);   // exp(-inf) = 0 handles the mask
            s[j] = p;
            psum += p;
        }
        psum += __shfl_xor_sync(0xffffffffu, psum, 1, 4);
        psum += __shfl_xor_sync(0xffffffffu, psum, 2, 4);
        l = l * alpha + psum;
#pragma unroll
        for (int i = 0; i < 16; i++) o[i] *= alpha;

        __syncthreads();   // everyone done reading KPs as K
        // ---- write P into KPs (alias): P[query][key] ----
        *(float4*)&KPs[query * FA_STRIDE + sub * 16 + 0]  = make_float4(s[0],  s[1],  s[2],  s[3]);
        *(float4*)&KPs[query * FA_STRIDE + sub * 16 + 4]  = make_float4(s[4],  s[5],  s[6],  s[7]);
        *(float4*)&KPs[query * FA_STRIDE + sub * 16 + 8]  = make_float4(s[8],  s[9],  s[10], s[11]);
        *(float4*)&KPs[query * FA_STRIDE + sub * 16 + 12] = make_float4(s[12], s[13], s[14], s[15]);
        __syncthreads();

        // ---- O += P @ V : this thread owns dims [sub*16 .. sub*16+15] ----
        for (int k = 0; k < 64; k++) {
            float p = KPs[query * FA_STRIDE + k];
            const float* vr = &Vs[k * FA_STRIDE + sub * 16];
#pragma unroll
            for (int i = 0; i < 16; i++) o[i] = fmaf(p, vr[i], o[i]);
        }
        m = m_new;
    }

    // ---- epilogue ----
    float inv = 1.f / l;
#pragma unroll
    for (int i = 0; i < 16; i++) o[i] *= inv;
    float* orow = &g_attn[(size_t)(b * T_SEQ + qg) * D_MODEL + h * HEAD_DIM + sub * 16];
    *(float4*)&orow[0]  = make_float4(o[0],  o[1],  o[2],  o[3]);
    *(float4*)&orow[4]  = make_float4(o[4],  o[5],  o[6],  o[7]);
    *(float4*)&orow[8]  = make_float4(o[8],  o[9],  o[10], o[11]);
    *(float4*)&orow[12] = make_float4(o[12], o[13], o[14], o[15]);
}

// ---------------------------------------------------------------------------
// Launch
// ---------------------------------------------------------------------------
extern "C" void kernel_launch(void* const* d_in, const int* in_sizes, int n_in,
                              void* d_out, int out_size) {
    const float* x     = (const float*)d_in[0];   // [2,2048,1024]
    const float* w_qkv = (const float*)d_in[1];   // [1024,3072]
    const float* w_out = (const float*)d_in[2];   // [1024,1024]
    float* out = (float*)d_out;                   // [2,2048,1024]

    void* qkv_ptr = nullptr;
    void* attn_ptr = nullptr;
    cudaGetSymbolAddress(&qkv_ptr, g_qkv);
    cudaGetSymbolAddress(&attn_ptr, g_attn);

    const int fa_smem = 3 * 64 * FA_STRIDE * (int)sizeof(float);  // 52224 B
    cudaFuncSetAttribute(flash_attn_kernel,
                         cudaFuncAttributeMaxDynamicSharedMemorySize, fa_smem);

    // 1) QKV projection: [4096,1024] @ [1024,3072]
    sgemm128<<<dim3(QKV_LD / 128, M_TOTAL / 128), 256>>>(
        x, w_qkv, (float*)qkv_ptr, M_TOTAL, QKV_LD, D_MODEL);

    // 2) causal flash attention per (b,h)
    flash_attn_kernel<<<dim3(T_SEQ / 64, BATCH * N_HEADS), 256, fa_smem>>>();

    // 3) output projection: [4096,1024] @ [1024,1024]
    sgemm128<<<dim3(D_MODEL / 128, M_TOTAL / 128), 256>>>(
        (const float*)attn_ptr, w_out, out, M_TOTAL, D_MODEL, D_MODEL);
}

// round 2
// speedup vs baseline: 2.3420x; 2.3420x over previous
#include <cuda_runtime.h>
#include <math.h>

// Problem constants
#define BATCH    2
#define T_SEQ    2048
#define D_MODEL  1024
#define N_HEADS  16
#define HEAD_DIM 64
#define M_TOTAL  (BATCH * T_SEQ)          // 4096 rows
#define QKV_LD   (3 * D_MODEL)            // 3072

// Scratch (allocation-free rule: __device__ globals)
__device__ float g_qkv [M_TOTAL * QKV_LD];   // [4096, 3072] : Q|K|V interleaved per row
__device__ float g_attn[M_TOTAL * D_MODEL];  // [4096, 1024] : attention output in [B,T,C]

// ---------------------------------------------------------------------------
// SGEMM: C[M,N] = A[M,K] @ B[K,N], all row-major, fp32.
// 128x128 block tile, K-step 8, 256 threads, 8x8 per-thread micro-tile.
// ---------------------------------------------------------------------------
__global__ __launch_bounds__(256) void sgemm128(const float* __restrict__ A,
                                                const float* __restrict__ B,
                                                float* __restrict__ C,
                                                int M, int N, int K) {
    __shared__ float As[8][128];   // transposed A tile: As[k][m]
    __shared__ float Bs[8][128];   // Bs[k][n]

    const int tid = threadIdx.x;
    const int row0 = blockIdx.y * 128;
    const int col0 = blockIdx.x * 128;
    const int tx = tid & 15;
    const int ty = tid >> 4;

    const int a_row = tid >> 1;
    const int a_k4  = (tid & 1) * 4;
    const int b_kr  = tid >> 5;
    const int b_c4  = (tid & 31) * 4;

    float acc[8][8];
#pragma unroll
    for (int i = 0; i < 8; i++)
#pragma unroll
        for (int j = 0; j < 8; j++) acc[i][j] = 0.f;

    for (int k0 = 0; k0 < K; k0 += 8) {
        float4 av = *(const float4*)&A[(size_t)(row0 + a_row) * K + k0 + a_k4];
        float4 bv = *(const float4*)&B[(size_t)(k0 + b_kr) * N + col0 + b_c4];
        As[a_k4 + 0][a_row] = av.x;
        As[a_k4 + 1][a_row] = av.y;
        As[a_k4 + 2][a_row] = av.z;
        As[a_k4 + 3][a_row] = av.w;
        *(float4*)&Bs[b_kr][b_c4] = bv;
        __syncthreads();

#pragma unroll
        for (int kk = 0; kk < 8; kk++) {
            float a[8], b[8];
            *(float4*)&a[0] = *(const float4*)&As[kk][ty * 8];
            *(float4*)&a[4] = *(const float4*)&As[kk][ty * 8 + 4];
            *(float4*)&b[0] = *(const float4*)&Bs[kk][tx * 4];
            *(float4*)&b[4] = *(const float4*)&Bs[kk][64 + tx * 4];
#pragma unroll
            for (int i = 0; i < 8; i++)
#pragma unroll
                for (int j = 0; j < 8; j++) acc[i][j] = fmaf(a[i], b[j], acc[i][j]);
        }
        __syncthreads();
    }

#pragma unroll
    for (int i = 0; i < 8; i++) {
        const int row = row0 + ty * 8 + i;
        float4 c0 = make_float4(acc[i][0], acc[i][1], acc[i][2], acc[i][3]);
        float4 c1 = make_float4(acc[i][4], acc[i][5], acc[i][6], acc[i][7]);
        *(float4*)&C[(size_t)row * N + col0 + tx * 4]      = c0;
        *(float4*)&C[(size_t)row * N + col0 + 64 + tx * 4] = c1;
    }
}

// ---------------------------------------------------------------------------
// Causal flash attention, fp32 SIMT, outer-product register tiling.
// grid = (T/128, B*H), 256 threads. 128-query block tile, 64-key tiles.
// Thread (tq = tid/16, tk = tid%16) owns an 8q x 4k micro-tile of S and an
// 8q x 4dv micro-tile of O. Both S = Q K^T and O += P V are rank-1-update
// loops: 32 FMA per 3 LDS.128 per step -> FMA-bound (balance needs >= 8:1 * 3/4).
// Softmax rows reduce across the 16 tk lanes (shfl widths 1,2,4,8 in 16-lane groups).
// ---------------------------------------------------------------------------
#define FA_QT 128
#define FA_KT 64
#define QS_STRIDE 132   // 128 + 4 pad
#define KS_STRIDE 68    // 64 + 4 pad
#define PS_STRIDE 132

#define FA_SMEM_FLOATS (64*QS_STRIDE + 64*KS_STRIDE + 64*KS_STRIDE + 64*PS_STRIDE)

__global__ __launch_bounds__(256, 2) void flash_attn_kernel() {
    extern __shared__ float sm[];
    float* Qs = sm;                                  // [64][132] d-major (Q^T)
    float* Ks = Qs + 64 * QS_STRIDE;                 // [64][68]  d-major (K^T)
    float* Vs = Ks + 64 * KS_STRIDE;                 // [64][68]  k-major (V natural)
    float* Ps = Vs + 64 * KS_STRIDE;                 // [64][132] k-major (P^T)

    const int tid = threadIdx.x;
    const int qt  = (gridDim.x - 1) - blockIdx.x;    // reversed: heavy tiles first
    const int bh  = blockIdx.y;
    const int b   = bh >> 4;
    const int h   = bh & 15;

    const float* base = g_qkv + (size_t)b * T_SEQ * QKV_LD + h * HEAD_DIM;
    const float* Qg = base;
    const float* Kg = base + D_MODEL;
    const float* Vg = base + 2 * D_MODEL;

    const int tq = tid >> 4;          // 0..15 : query rows tq*8 .. tq*8+7
    const int tk = tid & 15;          // 0..15 : key/dv cols tk*4 .. tk*4+3
    const int q0 = qt * FA_QT;

    // ---- load Q tile transposed: Qs[d][q], 128x64 ----
#pragma unroll
    for (int i = 0; i < 8; i++) {
        int ff = tid + i * 256;       // 0..2047
        int r  = ff >> 4;             // query 0..127
        int d4 = (ff & 15) * 4;
        float4 v = *(const float4*)&Qg[(size_t)(q0 + r) * QKV_LD + d4];
        Qs[(d4 + 0) * QS_STRIDE + r] = v.x;
        Qs[(d4 + 1) * QS_STRIDE + r] = v.y;
        Qs[(d4 + 2) * QS_STRIDE + r] = v.z;
        Qs[(d4 + 3) * QS_STRIDE + r] = v.w;
    }

    const float NEG_INF = __int_as_float(0xff800000u);
    const float scale = 0.125f;       // 1/sqrt(64)
    float m[8], l[8], o[8][4];
#pragma unroll
    for (int i = 0; i < 8; i++) {
        m[i] = NEG_INF; l[i] = 0.f;
#pragma unroll
        for (int j = 0; j < 4; j++) o[i][j] = 0.f;
    }

    const int nkt = 2 * qt + 2;
    for (int kt = 0; kt < nkt; kt++) {
        __syncthreads();              // prior iter's P/V reads done (covers Q load too)
        // ---- load K (transposed -> Ks[d][k]) and V (natural) ----
#pragma unroll
        for (int i = 0; i < 4; i++) {
            int ff = tid + i * 256;   // 0..1023
            int r  = ff >> 4;         // key row 0..63
            int d4 = (ff & 15) * 4;
            float4 kv = *(const float4*)&Kg[(size_t)(kt * FA_KT + r) * QKV_LD + d4];
            Ks[(d4 + 0) * KS_STRIDE + r] = kv.x;
            Ks[(d4 + 1) * KS_STRIDE + r] = kv.y;
            Ks[(d4 + 2) * KS_STRIDE + r] = kv.z;
            Ks[(d4 + 3) * KS_STRIDE + r] = kv.w;
            float4 vv = *(const float4*)&Vg[(size_t)(kt * FA_KT + r) * QKV_LD + d4];
            *(float4*)&Vs[r * KS_STRIDE + d4] = vv;
        }
        __syncthreads();

        // ---- S = Q K^T (outer product over d) ----
        float s[8][4];
#pragma unroll
        for (int i = 0; i < 8; i++)
#pragma unroll
            for (int j = 0; j < 4; j++) s[i][j] = 0.f;

#pragma unroll 8
        for (int d = 0; d < 64; d++) {
            float qv[8], kv[4];
            *(float4*)&qv[0] = *(const float4*)&Qs[d * QS_STRIDE + tq * 8];
            *(float4*)&qv[4] = *(const float4*)&Qs[d * QS_STRIDE + tq * 8 + 4];
            *(float4*)&kv[0] = *(const float4*)&Ks[d * KS_STRIDE + tk * 4];
#pragma unroll
            for (int i = 0; i < 8; i++)
#pragma unroll
                for (int j = 0; j < 4; j++) s[i][j] = fmaf(qv[i], kv[j], s[i][j]);
        }

        // ---- scale + causal mask (only tiles kt >= 2*qt touch the diagonal) ----
        const bool diag = (kt >= 2 * qt);
#pragma unroll
        for (int i = 0; i < 8; i++) {
            const int qg = q0 + tq * 8 + i;
#pragma unroll
            for (int j = 0; j < 4; j++) {
                s[i][j] *= scale;
                if (diag) {
                    int kg = kt * FA_KT + tk * 4 + j;
                    if (kg > qg) s[i][j] = NEG_INF;
                }
            }
        }

        // ---- online softmax: rows reduce across the 16 tk lanes ----
#pragma unroll
        for (int i = 0; i < 8; i++) {
            float tm = fmaxf(fmaxf(s[i][0], s[i][1]), fmaxf(s[i][2], s[i][3]));
            tm = fmaxf(tm, __shfl_xor_sync(0xffffffffu, tm, 1, 16));
            tm = fmaxf(tm, __shfl_xor_sync(0xffffffffu, tm, 2, 16));
            tm = fmaxf(tm, __shfl_xor_sync(0xffffffffu, tm, 4, 16));
            tm = fmaxf(tm, __shfl_xor_sync(0xffffffffu, tm, 8, 16));
            float m_new = fmaxf(m[i], tm);
            float alpha = __expf(m[i] - m_new);
            float psum = 0.f;
#pragma unroll
            for (int j = 0; j < 4; j++) {
                float p = __expf(s[i][j] - m_new);   // exp(-inf) = 0 handles mask
                s[i][j] = p;
                psum += p;
            }
            psum += __shfl_xor_sync(0xffffffffu, psum, 1, 16);
            psum += __shfl_xor_sync(0xffffffffu, psum, 2, 16);
            psum += __shfl_xor_sync(0xffffffffu, psum, 4, 16);
            psum += __shfl_xor_sync(0xffffffffu, psum, 8, 16);
            l[i] = l[i] * alpha + psum;
            m[i] = m_new;
#pragma unroll
            for (int j = 0; j < 4; j++) o[i][j] *= alpha;
        }

        // ---- store P transposed: Ps[k][q] ----
#pragma unroll
        for (int j = 0; j < 4; j++)
#pragma unroll
            for (int i = 0; i < 8; i++)
                Ps[(tk * 4 + j) * PS_STRIDE + tq * 8 + i] = s[i][j];
        __syncthreads();

        // ---- O += P V (outer product over k) ----
#pragma unroll 8
        for (int k = 0; k < 64; k++) {
            float pv[8], vv[4];
            *(float4*)&pv[0] = *(const float4*)&Ps[k * PS_STRIDE + tq * 8];
            *(float4*)&pv[4] = *(const float4*)&Ps[k * PS_STRIDE + tq * 8 + 4];
            *(float4*)&vv[0] = *(const float4*)&Vs[k * KS_STRIDE + tk * 4];
#pragma unroll
            for (int i = 0; i < 8; i++)
#pragma unroll
                for (int j = 0; j < 4; j++) o[i][j] = fmaf(pv[i], vv[j], o[i][j]);
        }
    }

    // ---- epilogue ----
#pragma unroll
    for (int i = 0; i < 8; i++) {
        float inv = 1.f / l[i];
        const int qg = q0 + tq * 8 + i;
        float4 c = make_float4(o[i][0] * inv, o[i][1] * inv, o[i][2] * inv, o[i][3] * inv);
        *(float4*)&g_attn[(size_t)(b * T_SEQ + qg) * D_MODEL + h * HEAD_DIM + tk * 4] = c;
    }
}

// ---------------------------------------------------------------------------
// Launch
// ---------------------------------------------------------------------------
extern "C" void kernel_launch(void* const* d_in, const int* in_sizes, int n_in,
                              void* d_out, int out_size) {
    const float* x     = (const float*)d_in[0];   // [2,2048,1024]
    const float* w_qkv = (const float*)d_in[1];   // [1024,3072]
    const float* w_out = (const float*)d_in[2];   // [1024,1024]
    float* out = (float*)d_out;                   // [2,2048,1024]

    void* qkv_ptr = nullptr;
    void* attn_ptr = nullptr;
    cudaGetSymbolAddress(&qkv_ptr, g_qkv);
    cudaGetSymbolAddress(&attn_ptr, g_attn);

    const int fa_smem = FA_SMEM_FLOATS * (int)sizeof(float);   // 102400 B
    cudaFuncSetAttribute(flash_attn_kernel,
                         cudaFuncAttributeMaxDynamicSharedMemorySize, fa_smem);

    // 1) QKV projection: [4096,1024] @ [1024,3072]
    sgemm128<<<dim3(QKV_LD / 128, M_TOTAL / 128), 256>>>(
        x, w_qkv, (float*)qkv_ptr, M_TOTAL, QKV_LD, D_MODEL);

    // 2) causal flash attention per (b,h)
    flash_attn_kernel<<<dim3(T_SEQ / FA_QT, BATCH * N_HEADS), 256, fa_smem>>>();

    // 3) output projection: [4096,1024] @ [1024,1024]
    sgemm128<<<dim3(D_MODEL / 128, M_TOTAL / 128), 256>>>(
        (const float*)attn_ptr, w_out, out, M_TOTAL, D_MODEL, D_MODEL);
}